// round 3
// baseline (speedup 1.0000x reference)
#include <cuda_runtime.h>
#include <math.h>

#define IMG_H 1500
#define IMG_W 2000
#define HW    (IMG_H * IMG_W)
#define NUM_V 10
#define MAX_EDGES 16384
#define NSLOT 32

// ---------------- device scratch (static; no runtime allocation) ----------------
__device__ float4 g_img1[HW];              // RGBA-interleaved image 1 (48 MB)
__device__ float4 g_img2[HW];              // RGBA-interleaved image 2 (48 MB)
__device__ float4 g_edges[MAX_EDGES * 3];  // per-edge: start, dir, up, len, num_h
__device__ double g_sim[NSLOT];
__device__ double g_nrm[NSLOT];
__device__ double g_nz[NSLOT];
__device__ unsigned long long g_cnt[NSLOT];
__device__ float  g_T[12];                 // rows 0..2 of K2h @ E2 @ inv(E1)

// ---------------- init: zero accumulators + compute T ----------------
__global__ void k_init(const float* __restrict__ K2,
                       const float* __restrict__ E1,
                       const float* __restrict__ E2) {
    int t = threadIdx.x;
    if (t < NSLOT) { g_sim[t] = 0.0; g_nrm[t] = 0.0; g_nz[t] = 0.0; g_cnt[t] = 0ull; }
    if (t == 0) {
        // Gauss-Jordan inverse of E1 in double
        double a[4][8];
        for (int i = 0; i < 4; i++)
            for (int j = 0; j < 4; j++) {
                a[i][j] = (double)E1[i * 4 + j];
                a[i][4 + j] = (i == j) ? 1.0 : 0.0;
            }
        for (int c = 0; c < 4; c++) {
            int p = c; double mx = fabs(a[c][c]);
            for (int r = c + 1; r < 4; r++) {
                double v = fabs(a[r][c]);
                if (v > mx) { mx = v; p = r; }
            }
            if (p != c)
                for (int j = 0; j < 8; j++) { double tmp = a[c][j]; a[c][j] = a[p][j]; a[p][j] = tmp; }
            double pv = a[c][c];
            for (int j = 0; j < 8; j++) a[c][j] /= pv;
            for (int r = 0; r < 4; r++)
                if (r != c) {
                    double f = a[r][c];
                    for (int j = 0; j < 8; j++) a[r][j] -= f * a[c][j];
                }
        }
        double M[4][4];
        for (int i = 0; i < 4; i++)
            for (int j = 0; j < 4; j++) {
                double s = 0.0;
                for (int k = 0; k < 4; k++) s += (double)E2[i * 4 + k] * a[k][4 + j];
                M[i][j] = s;
            }
        // T rows 0..2 : K2h row r has K2[r,0..2] and 0 in col 3
        for (int r = 0; r < 3; r++)
            for (int j = 0; j < 4; j++) {
                double s = 0.0;
                for (int k = 0; k < 3; k++) s += (double)K2[r * 3 + k] * M[k][j];
                g_T[r * 4 + j] = (float)s;
            }
    }
}

// ---------------- pack planar (3,H,W) -> interleaved float4 ----------------
__global__ void k_pack(const float* __restrict__ src, int which) {
    int i = blockIdx.x * blockDim.x + threadIdx.x;
    if (i < HW) {
        float4 v = make_float4(src[i], src[i + HW], src[i + 2 * HW], 0.0f);
        if (which) g_img2[i] = v; else g_img1[i] = v;
    }
}

// ---------------- per-edge prep + normal losses ----------------
__global__ void k_edge(const float* __restrict__ ep, int N) {
    int i = blockIdx.x * blockDim.x + threadIdx.x;
    if (i >= N) return;
    const float* e = ep + (size_t)i * 12;
    float p0x = e[0],  p0y = e[1],  p0z = e[2];
    float p1x = e[3],  p1y = e[4],  p1z = e[5];
    float p2x = e[6],  p2y = e[7],  p2z = e[8];
    float p3x = e[9],  p3y = e[10], p3z = e[11];

    float cdx = p1x - p0x, cdy = p1y - p0y, cdz = p1z - p0z;
    float ax = cdx + 1e-6f, ay = cdy + 1e-6f, az = cdz + 1e-6f;
    float clen = sqrtf(ax * ax + ay * ay + az * az);

    int numh = (int)floorf(clen / 0.05f);
    numh = numh < 2 ? 2 : (numh > 1000 ? 1000 : numh);

    float dx = cdx / clen, dy = cdy / clen, dz = cdz / clen;
    float nxd = p3x - p1x, nyd = p3y - p1y, nzd = p3z - p1z;
    float pxd = p0x - p2x, pyd = p0y - p2y, pzd = p0z - p2z;

    // cur_normal = normalize(cross(cur_dir, next_dir)), flipped if z>0
    float cnx = dy * nzd - dz * nyd;
    float cny = dz * nxd - dx * nzd;
    float cnz = dx * nyd - dy * nxd;
    float nn = sqrtf(cnx * cnx + cny * cny + cnz * cnz) + 1e-6f;
    cnx /= nn; cny /= nn; cnz /= nn;
    if (cnz > 0.0f) { cnx = -cnx; cny = -cny; cnz = -cnz; }

    // cur_up = normalize(cross(cur_normal, cur_dir))
    float ux = cny * dz - cnz * dy;
    float uy = cnz * dx - cnx * dz;
    float uz = cnx * dy - cny * dx;
    float un = sqrtf(ux * ux + uy * uy + uz * uz) + 1e-6f;
    ux /= un; uy /= un; uz /= un;

    // prev_normal = normalize(cross(prev_dir, cur_dir))
    float pnx = pyd * dz - pzd * dy;
    float pny = pzd * dx - pxd * dz;
    float pnz = pxd * dy - pyd * dx;
    float pn = sqrtf(pnx * pnx + pny * pny + pnz * pnz) + 1e-6f;
    pnx /= pn; pny /= pn; pnz /= pn;
    float nterm = 1.0f - (cnx * pnx + cny * pny + cnz * pnz);

    // obs_normal = normalize(cross(p0, p1))
    float ox = p0y * p1z - p0z * p1y;
    float oy = p0z * p1x - p0x * p1z;
    float oz = p0x * p1y - p0y * p1x;
    float on = sqrtf(ox * ox + oy * oy + oz * oz) + 1e-6f;
    ox /= on; oy /= on; oz /= on;
    float snp = fminf(fabsf(ux * ox + uy * oy + uz * oz), 0.5f);
    float zterm = 1.0f - snp * 2.0f;

    int slot = i & (NSLOT - 1);
    atomicAdd(&g_nrm[slot], (double)nterm);
    atomicAdd(&g_nz[slot], (double)zterm);
    atomicAdd(&g_cnt[slot], (unsigned long long)numh);

    g_edges[i * 3 + 0] = make_float4(p0x, p0y, p0z, dx);
    g_edges[i * 3 + 1] = make_float4(dy, dz, ux, uy);
    g_edges[i * 3 + 2] = make_float4(uz, clen, __int_as_float(numh), 0.0f);
}

// ---------------- bilinear sample from interleaved float4 image ----------------
__device__ __forceinline__ float3 bilerp(const float4* __restrict__ im, float uu, float vv) {
    float x = uu * (float)(IMG_W - 1);
    float y = vv * (float)(IMG_H - 1);
    float fx = floorf(x), fy = floorf(y);
    float wx = x - fx, wy = y - fy;
    int b = (int)fy * IMG_W + (int)fx;   // fx<=W-2, fy<=H-2 guaranteed by clip
    float4 v00 = __ldg(im + b);
    float4 v01 = __ldg(im + b + 1);
    float4 v10 = __ldg(im + b + IMG_W);
    float4 v11 = __ldg(im + b + IMG_W + 1);
    float w00 = (1.0f - wx) * (1.0f - wy);
    float w01 = wx * (1.0f - wy);
    float w10 = (1.0f - wx) * wy;
    float w11 = wx * wy;
    float3 r;
    r.x = v00.x * w00 + v01.x * w01 + v10.x * w10 + v11.x * w11;
    r.y = v00.y * w00 + v01.y * w01 + v10.y * w10 + v11.y * w11;
    r.z = v00.z * w00 + v01.z * w01 + v10.z * w10 + v11.z * w11;
    return r;
}

// ---------------- per-point sampling + similarity loss (1 block per edge) ----------------
__global__ void __launch_bounds__(256) k_sample(const float* __restrict__ K1g) {
    int e = blockIdx.x;
    float4 A = g_edges[e * 3 + 0];
    float4 B = g_edges[e * 3 + 1];
    float4 C = g_edges[e * 3 + 2];
    float sx = A.x, sy = A.y, sz = A.z;
    float dx = A.w, dy = B.x, dz = B.y;
    float ux = B.z, uy = B.w, uz = C.x;
    float len = C.y;
    int numh = __float_as_int(C.z);
    int total = numh * NUM_V;
    float inv_denom = 1.0f / (float)(numh - 1);

    float K0 = __ldg(K1g + 0), K1 = __ldg(K1g + 1), K2 = __ldg(K1g + 2);
    float K3 = __ldg(K1g + 3), K4 = __ldg(K1g + 4), K5 = __ldg(K1g + 5);
    float K6 = __ldg(K1g + 6), K7 = __ldg(K1g + 7), K8 = __ldg(K1g + 8);
    float T[12];
#pragma unroll
    for (int j = 0; j < 12; j++) T[j] = g_T[j];

    const float inv9h = (1.0f / 9.0f) * 0.5f;
    float lsum = 0.0f;
    for (int t = threadIdx.x; t < total; t += 256) {
        int ix = t / NUM_V;
        int dv = t - ix * NUM_V;
        float cx = ((float)ix * inv_denom) * len;
        float cy = (float)dv * inv9h;
        float px = fmaf(dx, cx, fmaf(ux, cy, sx));
        float py = fmaf(dy, cx, fmaf(uy, cy, sy));
        float pz = fmaf(dz, cx, fmaf(uz, cy, sz));

        // view 1 projection
        float u1 = K0 * px + K1 * py + K2 * pz;
        float v1 = K3 * px + K4 * py + K5 * pz;
        float w1 = K6 * px + K7 * py + K8 * pz;
        float iw1 = 1.0f / w1;
        float uu1 = fminf(fmaxf(u1 * iw1, 0.0f), 0.999999f);
        float vv1 = fminf(fmaxf(v1 * iw1, 0.0f), 0.999999f);

        // view 2 projection (homogeneous, T rows)
        float u2 = fmaf(T[0], px, fmaf(T[1], py, fmaf(T[2], pz, T[3])));
        float v2 = fmaf(T[4], px, fmaf(T[5], py, fmaf(T[6], pz, T[7])));
        float w2 = fmaf(T[8], px, fmaf(T[9], py, fmaf(T[10], pz, T[11])));
        float iw2 = 1.0f / w2;
        float uu2 = fminf(fmaxf(u2 * iw2, 0.0f), 0.999999f);
        float vv2 = fminf(fmaxf(v2 * iw2, 0.0f), 0.999999f);

        float3 s1 = bilerp(g_img1, uu1, vv1);
        float3 s2 = bilerp(g_img2, uu2, vv2);
        float d0 = s1.x - s2.x, d1 = s1.y - s2.y, d2 = s1.z - s2.z;
        lsum = fmaf(d0, d0, fmaf(d1, d1, fmaf(d2, d2, lsum)));
    }

    // block reduction: warp shuffle -> shared -> one double atomic per block
#pragma unroll
    for (int o = 16; o > 0; o >>= 1) lsum += __shfl_down_sync(0xffffffffu, lsum, o);
    __shared__ float ws[8];
    int lane = threadIdx.x & 31, w = threadIdx.x >> 5;
    if (lane == 0) ws[w] = lsum;
    __syncthreads();
    if (threadIdx.x == 0) {
        float s = 0.0f;
#pragma unroll
        for (int j = 0; j < 8; j++) s += ws[j];
        atomicAdd(&g_sim[e & (NSLOT - 1)], (double)s);
    }
}

// ---------------- finalize ----------------
__global__ void k_final(float* __restrict__ out, int N) {
    if (threadIdx.x == 0 && blockIdx.x == 0) {
        double sim = 0.0, nrm = 0.0, nz = 0.0;
        unsigned long long cnt = 0ull;
        for (int i = 0; i < NSLOT; i++) {
            sim += g_sim[i]; nrm += g_nrm[i]; nz += g_nz[i]; cnt += g_cnt[i];
        }
        double npts = (double)cnt * (double)NUM_V;     // total sampled points
        out[0] = (float)(sim / (npts * 3.0));
        out[1] = (float)(nrm / (2.0 * (double)N));
        out[2] = (float)(nz / (double)N);
    }
}

// ---------------- launch ----------------
extern "C" void kernel_launch(void* const* d_in, const int* in_sizes, int n_in,
                              void* d_out, int out_size) {
    const float* ep   = (const float*)d_in[0];
    const float* K1   = (const float*)d_in[1];
    const float* K2   = (const float*)d_in[2];
    const float* E1   = (const float*)d_in[3];
    const float* E2   = (const float*)d_in[4];
    const float* rgb1 = (const float*)d_in[5];
    const float* rgb2 = (const float*)d_in[6];

    int N = in_sizes[0] / 12;
    if (N > MAX_EDGES) N = MAX_EDGES;

    k_init<<<1, 32>>>(K2, E1, E2);
    int pb = (HW + 255) / 256;
    k_pack<<<pb, 256>>>(rgb1, 0);
    k_pack<<<pb, 256>>>(rgb2, 1);
    k_edge<<<(N + 255) / 256, 256>>>(ep, N);
    k_sample<<<N, 256>>>(K1);
    k_final<<<1, 1>>>((float*)d_out, N);
}

// round 4
// speedup vs baseline: 1.3352x; 1.3352x over previous
#include <cuda_runtime.h>
#include <cuda_fp16.h>
#include <math.h>

#define IMG_H 1500
#define IMG_W 2000
#define HW    (IMG_H * IMG_W)
#define NUM_V 10
#define MAX_EDGES 16384
#define NSLOT 32

// ---------------- device scratch (static; no runtime allocation) ----------------
// Paired-pixel fp16 layout: entry i = pixels (i, i+1) as r0,g0,b0,r1,g1,b1 halves
// packed into one 16B uint4. One LDG.128 fetches a full horizontal tap pair.
__device__ uint4 g_img1[HW];   // 48 MB
__device__ uint4 g_img2[HW];   // 48 MB
__device__ double g_sim[NSLOT];
__device__ double g_nrm[NSLOT];
__device__ double g_nz[NSLOT];
__device__ unsigned long long g_cnt[NSLOT];
__device__ float  g_T[12];     // rows 0..2 of K2h @ E2 @ inv(E1)

// ---------------- init: zero accumulators + compute T ----------------
__global__ void k_init(const float* __restrict__ K2,
                       const float* __restrict__ E1,
                       const float* __restrict__ E2) {
    int t = threadIdx.x;
    if (t < NSLOT) { g_sim[t] = 0.0; g_nrm[t] = 0.0; g_nz[t] = 0.0; g_cnt[t] = 0ull; }
    if (t == 0) {
        double a[4][8];
        for (int i = 0; i < 4; i++)
            for (int j = 0; j < 4; j++) {
                a[i][j] = (double)E1[i * 4 + j];
                a[i][4 + j] = (i == j) ? 1.0 : 0.0;
            }
        for (int c = 0; c < 4; c++) {
            int p = c; double mx = fabs(a[c][c]);
            for (int r = c + 1; r < 4; r++) {
                double v = fabs(a[r][c]);
                if (v > mx) { mx = v; p = r; }
            }
            if (p != c)
                for (int j = 0; j < 8; j++) { double tmp = a[c][j]; a[c][j] = a[p][j]; a[p][j] = tmp; }
            double pv = a[c][c];
            for (int j = 0; j < 8; j++) a[c][j] /= pv;
            for (int r = 0; r < 4; r++)
                if (r != c) {
                    double f = a[r][c];
                    for (int j = 0; j < 8; j++) a[r][j] -= f * a[c][j];
                }
        }
        double M[4][4];
        for (int i = 0; i < 4; i++)
            for (int j = 0; j < 4; j++) {
                double s = 0.0;
                for (int k = 0; k < 4; k++) s += (double)E2[i * 4 + k] * a[k][4 + j];
                M[i][j] = s;
            }
        for (int r = 0; r < 3; r++)
            for (int j = 0; j < 4; j++) {
                double s = 0.0;
                for (int k = 0; k < 3; k++) s += (double)K2[r * 3 + k] * M[k][j];
                g_T[r * 4 + j] = (float)s;
            }
    }
}

// ---------------- pack both planar images -> paired fp16 entries ----------------
__global__ void k_pack(const float* __restrict__ r1, const float* __restrict__ r2) {
    int i = blockIdx.x * blockDim.x + threadIdx.x;
    if (i >= 2 * HW) return;
    const float* src = (i < HW) ? r1 : r2;
    uint4* dst       = (i < HW) ? g_img1 : g_img2;
    int j  = (i < HW) ? i : i - HW;
    int jn = j + 1 < HW ? j + 1 : HW - 1;

    float a0 = src[j],       a1 = src[j + HW],       a2 = src[j + 2 * HW];
    float b0 = src[jn],      b1 = src[jn + HW],      b2 = src[jn + 2 * HW];

    __half2 h0 = __floats2half2_rn(a0, a1);   // r0,g0
    __half2 h1 = __floats2half2_rn(a2, b0);   // b0,r1
    __half2 h2 = __floats2half2_rn(b1, b2);   // g1,b1
    uint4 v;
    v.x = *reinterpret_cast<unsigned int*>(&h0);
    v.y = *reinterpret_cast<unsigned int*>(&h1);
    v.z = *reinterpret_cast<unsigned int*>(&h2);
    v.w = 0u;
    dst[j] = v;
}

// ---------------- bilinear sample from paired fp16 image (2 LDG.128 per sample) --
__device__ __forceinline__ float3 bilerp(const uint4* __restrict__ im, float uu, float vv) {
    float x = uu * (float)(IMG_W - 1);
    float y = vv * (float)(IMG_H - 1);
    float fx = floorf(x), fy = floorf(y);
    float wx = x - fx, wy = y - fy;
    int b = (int)fy * IMG_W + (int)fx;        // fx<=W-2, fy<=H-2 guaranteed by clip

    uint4 t = __ldg(im + b);                  // row y0: pixels x0,x1
    uint4 u = __ldg(im + b + IMG_W);          // row y1: pixels x0,x1

    float2 t0 = __half22float2(*reinterpret_cast<const __half2*>(&t.x));  // r0,g0
    float2 t1 = __half22float2(*reinterpret_cast<const __half2*>(&t.y));  // b0,r1
    float2 t2 = __half22float2(*reinterpret_cast<const __half2*>(&t.z));  // g1,b1
    float2 u0 = __half22float2(*reinterpret_cast<const __half2*>(&u.x));
    float2 u1 = __half22float2(*reinterpret_cast<const __half2*>(&u.y));
    float2 u2 = __half22float2(*reinterpret_cast<const __half2*>(&u.z));

    float iwx = 1.0f - wx;
    // horizontal lerp per row
    float tr = t0.x * iwx + t1.y * wx;
    float tg = t0.y * iwx + t2.x * wx;
    float tb = t1.x * iwx + t2.y * wx;
    float ur = u0.x * iwx + u1.y * wx;
    float ug = u0.y * iwx + u2.x * wx;
    float ub = u1.x * iwx + u2.y * wx;
    // vertical lerp
    float iwy = 1.0f - wy;
    float3 r;
    r.x = tr * iwy + ur * wy;
    r.y = tg * iwy + ug * wy;
    r.z = tb * iwy + ub * wy;
    return r;
}

// ---------------- per-edge prep + sampling + all losses (1 block per edge) -------
__global__ void __launch_bounds__(128) k_sample(const float* __restrict__ ep,
                                                const float* __restrict__ K1g) {
    int e = blockIdx.x;
    const float* pe = ep + (size_t)e * 12;
    float p0x = pe[0],  p0y = pe[1],  p0z = pe[2];
    float p1x = pe[3],  p1y = pe[4],  p1z = pe[5];
    float p2x = pe[6],  p2y = pe[7],  p2z = pe[8];
    float p3x = pe[9],  p3y = pe[10], p3z = pe[11];

    float cdx = p1x - p0x, cdy = p1y - p0y, cdz = p1z - p0z;
    float ax = cdx + 1e-6f, ay = cdy + 1e-6f, az = cdz + 1e-6f;
    float clen = sqrtf(ax * ax + ay * ay + az * az);

    int numh = (int)floorf(clen / 0.05f);
    numh = numh < 2 ? 2 : (numh > 1000 ? 1000 : numh);

    float dx = cdx / clen, dy = cdy / clen, dz = cdz / clen;
    float nxd = p3x - p1x, nyd = p3y - p1y, nzd = p3z - p1z;

    // cur_normal = normalize(cross(cur_dir, next_dir)), flipped if z>0
    float cnx = dy * nzd - dz * nyd;
    float cny = dz * nxd - dx * nzd;
    float cnz = dx * nyd - dy * nxd;
    float nn = sqrtf(cnx * cnx + cny * cny + cnz * cnz) + 1e-6f;
    cnx /= nn; cny /= nn; cnz /= nn;
    if (cnz > 0.0f) { cnx = -cnx; cny = -cny; cnz = -cnz; }

    // cur_up = normalize(cross(cur_normal, cur_dir))
    float ux = cny * dz - cnz * dy;
    float uy = cnz * dx - cnx * dz;
    float uz = cnx * dy - cny * dx;
    float un = sqrtf(ux * ux + uy * uy + uz * uz) + 1e-6f;
    ux /= un; uy /= un; uz /= un;

    // thread 0: the two per-edge losses + point count
    if (threadIdx.x == 0) {
        float pxd = p0x - p2x, pyd = p0y - p2y, pzd = p0z - p2z;
        float pnx = pyd * dz - pzd * dy;
        float pny = pzd * dx - pxd * dz;
        float pnz = pxd * dy - pyd * dx;
        float pn = sqrtf(pnx * pnx + pny * pny + pnz * pnz) + 1e-6f;
        float nterm = 1.0f - (cnx * pnx + cny * pny + cnz * pnz) / pn;

        float ox = p0y * p1z - p0z * p1y;
        float oy = p0z * p1x - p0x * p1z;
        float oz = p0x * p1y - p0y * p1x;
        float on = sqrtf(ox * ox + oy * oy + oz * oz) + 1e-6f;
        float snp = fminf(fabsf((ux * ox + uy * oy + uz * oz) / on), 0.5f);
        float zterm = 1.0f - snp * 2.0f;

        int slot = e & (NSLOT - 1);
        atomicAdd(&g_nrm[slot], (double)nterm);
        atomicAdd(&g_nz[slot], (double)zterm);
        atomicAdd(&g_cnt[slot], (unsigned long long)numh);
    }

    float K0 = __ldg(K1g + 0), K1 = __ldg(K1g + 1), K2 = __ldg(K1g + 2);
    float K3 = __ldg(K1g + 3), K4 = __ldg(K1g + 4), K5 = __ldg(K1g + 5);
    float K6 = __ldg(K1g + 6), K7 = __ldg(K1g + 7), K8 = __ldg(K1g + 8);
    float T[12];
#pragma unroll
    for (int j = 0; j < 12; j++) T[j] = g_T[j];

    int total = numh * NUM_V;
    float inv_denom = 1.0f / (float)(numh - 1);
    const float inv9h = (1.0f / 9.0f) * 0.5f;
    float lsum = 0.0f;

    for (int t = threadIdx.x; t < total; t += 128) {
        int ix = t / NUM_V;
        int dv = t - ix * NUM_V;
        float cx = ((float)ix * inv_denom) * clen;
        float cy = (float)dv * inv9h;
        float px = fmaf(dx, cx, fmaf(ux, cy, p0x));
        float py = fmaf(dy, cx, fmaf(uy, cy, p0y));
        float pz = fmaf(dz, cx, fmaf(uz, cy, p0z));

        // view 1 projection
        float u1 = K0 * px + K1 * py + K2 * pz;
        float v1 = K3 * px + K4 * py + K5 * pz;
        float w1 = K6 * px + K7 * py + K8 * pz;
        float iw1 = 1.0f / w1;
        float uu1 = fminf(fmaxf(u1 * iw1, 0.0f), 0.999999f);
        float vv1 = fminf(fmaxf(v1 * iw1, 0.0f), 0.999999f);

        // view 2 projection (homogeneous)
        float u2 = fmaf(T[0], px, fmaf(T[1], py, fmaf(T[2], pz, T[3])));
        float v2 = fmaf(T[4], px, fmaf(T[5], py, fmaf(T[6], pz, T[7])));
        float w2 = fmaf(T[8], px, fmaf(T[9], py, fmaf(T[10], pz, T[11])));
        float iw2 = 1.0f / w2;
        float uu2 = fminf(fmaxf(u2 * iw2, 0.0f), 0.999999f);
        float vv2 = fminf(fmaxf(v2 * iw2, 0.0f), 0.999999f);

        float3 s1 = bilerp(g_img1, uu1, vv1);
        float3 s2 = bilerp(g_img2, uu2, vv2);
        float d0 = s1.x - s2.x, d1 = s1.y - s2.y, d2 = s1.z - s2.z;
        lsum = fmaf(d0, d0, fmaf(d1, d1, fmaf(d2, d2, lsum)));
    }

    // block reduction: warp shuffle -> shared -> one double atomic per block
#pragma unroll
    for (int o = 16; o > 0; o >>= 1) lsum += __shfl_down_sync(0xffffffffu, lsum, o);
    __shared__ float ws[4];
    int lane = threadIdx.x & 31, w = threadIdx.x >> 5;
    if (lane == 0) ws[w] = lsum;
    __syncthreads();
    if (threadIdx.x == 0) {
        float s = ws[0] + ws[1] + ws[2] + ws[3];
        atomicAdd(&g_sim[e & (NSLOT - 1)], (double)s);
    }
}

// ---------------- finalize ----------------
__global__ void k_final(float* __restrict__ out, int N) {
    if (threadIdx.x == 0 && blockIdx.x == 0) {
        double sim = 0.0, nrm = 0.0, nz = 0.0;
        unsigned long long cnt = 0ull;
        for (int i = 0; i < NSLOT; i++) {
            sim += g_sim[i]; nrm += g_nrm[i]; nz += g_nz[i]; cnt += g_cnt[i];
        }
        double npts = (double)cnt * (double)NUM_V;
        out[0] = (float)(sim / (npts * 3.0));
        out[1] = (float)(nrm / (2.0 * (double)N));
        out[2] = (float)(nz / (double)N);
    }
}

// ---------------- launch ----------------
extern "C" void kernel_launch(void* const* d_in, const int* in_sizes, int n_in,
                              void* d_out, int out_size) {
    const float* ep   = (const float*)d_in[0];
    const float* K1   = (const float*)d_in[1];
    const float* K2   = (const float*)d_in[2];
    const float* E1   = (const float*)d_in[3];
    const float* E2   = (const float*)d_in[4];
    const float* rgb1 = (const float*)d_in[5];
    const float* rgb2 = (const float*)d_in[6];

    int N = in_sizes[0] / 12;
    if (N > MAX_EDGES) N = MAX_EDGES;

    k_init<<<1, 32>>>(K2, E1, E2);
    k_pack<<<(2 * HW + 255) / 256, 256>>>(rgb1, rgb2);
    k_sample<<<N, 128>>>(ep, K1);
    k_final<<<1, 1>>>((float*)d_out, N);
}